// round 17
// baseline (speedup 1.0000x reference)
#include <cuda_runtime.h>
#include <cuda_bf16.h>
#include <math.h>
#include <cstdint>

#define H    8
#define BB   8
#define NN   1024
#define FIN  512
#define FOUT 256
#define ALPHA 0.2f

// Scratch (device globals per harness allocation rules)
__device__ float g_f1[H * BB * NN];
__device__ float g_f2[H * BB * NN];
__device__ float g_c1[H * FIN];
__device__ float g_c2[H * FIN];
__device__ __nv_bfloat16 g_xh[(size_t)BB * NN * FIN];
__device__ __nv_bfloat16 g_wh[(size_t)H * FOUT * FIN];
__device__ __nv_bfloat16 g_hh[(size_t)H * BB * NN * FOUT];   // h bf16 hi

// ---- ldmatrix / mma.sync helpers (sm_80-era PTX, valid on plain sm_103) ---
__device__ __forceinline__ uint32_t smem_u32(const void* p) {
    uint32_t a;
    asm("{ .reg .u64 t; cvta.to.shared.u64 t, %1; cvt.u32.u64 %0, t; }" : "=r"(a) : "l"(p));
    return a;
}
#define LDMX4(r0, r1, r2, r3, a) \
    asm volatile("ldmatrix.sync.aligned.m8n8.x4.shared.b16 {%0,%1,%2,%3}, [%4];" \
                 : "=r"(r0), "=r"(r1), "=r"(r2), "=r"(r3) : "r"(a))
#define LDMX4T(r0, r1, r2, r3, a) \
    asm volatile("ldmatrix.sync.aligned.m8n8.x4.trans.shared.b16 {%0,%1,%2,%3}, [%4];" \
                 : "=r"(r0), "=r"(r1), "=r"(r2), "=r"(r3) : "r"(a))
#define MMA16816(d, a0, a1, a2, a3, b0, b1) \
    asm volatile("mma.sync.aligned.m16n8k16.row.col.f32.bf16.bf16.f32 " \
                 "{%0,%1,%2,%3},{%4,%5,%6,%7},{%8,%9},{%0,%1,%2,%3};" \
                 : "+f"((d)[0]), "+f"((d)[1]), "+f"((d)[2]), "+f"((d)[3]) \
                 : "r"(a0), "r"(a1), "r"(a2), "r"(a3), "r"(b0), "r"(b1))
#define CPA16(dst, src) \
    asm volatile("cp.async.cg.shared.global [%0], [%1], 16;" :: "r"(dst), "l"(src) : "memory")
#define CP_COMMIT() asm volatile("cp.async.commit_group;" ::: "memory")
#define CP_WAIT0()  asm volatile("cp.async.wait_group 0;" ::: "memory")
#define CP_WAIT1()  asm volatile("cp.async.wait_group 1;" ::: "memory")
// cvt d, a, b -> d.hi = a, d.lo = b
#define CVT_BF2(q, hi, lo) \
    asm("cvt.rn.bf16x2.f32 %0, %1, %2;" : "=r"(q) : "f"(hi), "f"(lo))

__device__ __forceinline__ uint32_t lmaddr(uint32_t base, int row, int chunk) {
    return base + row * 128 + (((chunk) ^ (row & 7)) << 4);
}

// ---------------------------------------------------------------------------
// Kernel A: fused split (bf16 convert) + c12 (W^T a) — independent block ranges
// blocks [0,1280): convert; blocks [1280,1288): c12 per head. 512 threads.
// ---------------------------------------------------------------------------
#define SPLIT_BLOCKS 1280

__global__ __launch_bounds__(512) void prepA_kernel(const float* __restrict__ x,
                                                    const float* __restrict__ W,
                                                    const float* __restrict__ a1,
                                                    const float* __restrict__ a2)
{
    if (blockIdx.x < SPLIT_BLOCKS) {
        const size_t NX = (size_t)BB * NN * FIN;
        const size_t NW = (size_t)H * FOUT * FIN;
        size_t i = (size_t)blockIdx.x * 512 + threadIdx.x;
        size_t stride = (size_t)SPLIT_BLOCKS * 512;
        for (; i < NX + NW; i += stride) {
            if (i < NX) g_xh[i] = __float2bfloat16_rn(x[i]);
            else        g_wh[i - NX] = __float2bfloat16_rn(W[i - NX]);
        }
    } else {
        __shared__ float a1s[FOUT], a2s[FOUT];
        const int hd = blockIdx.x - SPLIT_BLOCKS;
        const int f = threadIdx.x;
        for (int i = threadIdx.x; i < FOUT; i += 512) {
            a1s[i] = a1[hd * FOUT + i];
            a2s[i] = a2[hd * FOUT + i];
        }
        __syncthreads();
        const float* Wp = W + (size_t)hd * FOUT * FIN + f;
        float s1 = 0.f, s2 = 0.f;
#pragma unroll 4
        for (int o = 0; o < FOUT; o++) {
            float w = Wp[(size_t)o * FIN];
            s1 = fmaf(w, a1s[o], s1);
            s2 = fmaf(w, a2s[o], s2);
        }
        g_c1[hd * FIN + f] = s1;
        g_c2[hd * FIN + f] = s2;
    }
}

// ---------------------------------------------------------------------------
// Kernel B: fused gemm_h (y<2) + f12x (y>=2). Both depend only on prepA.
// grid (64, 4, 8), 256 threads, 64KB dynamic smem.
// ---------------------------------------------------------------------------
#define G_A 0
#define G_B 16384
#define G_STAGE 32768
#define G_TOTAL 65536

__device__ __forceinline__ void f12x_body(const float* __restrict__ x, int blk,
                                          char* smraw)
{
    float* cs = (float*)smraw;   // 32 KB of the 64KB dynamic buffer
    for (int i = threadIdx.x; i < H * FIN; i += 256) {
        cs[i] = g_c1[i];
        cs[H * FIN + i] = g_c2[i];
    }
    __syncthreads();
    const int w = threadIdx.x >> 5, lane = threadIdx.x & 31;
    const int r = blk * 8 + w;
    const float* xp = x + (size_t)r * FIN;
    float acc1[8], acc2[8];
#pragma unroll
    for (int hd = 0; hd < 8; hd++) { acc1[hd] = 0.f; acc2[hd] = 0.f; }
#pragma unroll
    for (int i = 0; i < 4; i++) {
        const int off = lane * 4 + i * 128;
        float4 xv = *(const float4*)(xp + off);
#pragma unroll
        for (int hd = 0; hd < 8; hd++) {
            float4 cv = *(const float4*)(cs + hd * FIN + off);
            acc1[hd] = fmaf(xv.x, cv.x, fmaf(xv.y, cv.y, fmaf(xv.z, cv.z, fmaf(xv.w, cv.w, acc1[hd]))));
            float4 dv = *(const float4*)(cs + H * FIN + hd * FIN + off);
            acc2[hd] = fmaf(xv.x, dv.x, fmaf(xv.y, dv.y, fmaf(xv.z, dv.z, fmaf(xv.w, dv.w, acc2[hd]))));
        }
    }
#pragma unroll
    for (int hd = 0; hd < 8; hd++) {
#pragma unroll
        for (int off = 16; off; off >>= 1) {
            acc1[hd] += __shfl_xor_sync(0xffffffffu, acc1[hd], off);
            acc2[hd] += __shfl_xor_sync(0xffffffffu, acc2[hd], off);
        }
    }
    if (lane == 0) {
#pragma unroll
        for (int hd = 0; hd < 8; hd++) {
            g_f1[hd * (BB * NN) + r] = acc1[hd];
            g_f2[hd * (BB * NN) + r] = acc2[hd];
        }
    }
}

__global__ __launch_bounds__(256) void prepB_kernel(const float* __restrict__ x)
{
    extern __shared__ char sm[];
    if (blockIdx.y >= 2) {
        int blk = ((int)blockIdx.z * 64 + (int)blockIdx.x) * 2 + ((int)blockIdx.y - 2);
        f12x_body(x, blk, sm);
        return;
    }

    const uint32_t sb = smem_u32(sm);
    const int tid = threadIdx.x;
    const int wid = tid >> 5;
    const int lane = tid & 31;
    const int m0 = blockIdx.x * 128;
    const int o0 = blockIdx.y * 128;
    const int hd = blockIdx.z;
    const int warp_m = (wid & 3) * 32;
    const int warp_n = (wid >> 2) * 64;

    float d[2][8][4];
#pragma unroll
    for (int i = 0; i < 2; i++)
#pragma unroll
        for (int j = 0; j < 8; j++)
#pragma unroll
            for (int c = 0; c < 4; c++) d[i][j][c] = 0.f;

    const char* xh = (const char*)g_xh + (size_t)m0 * FIN * 2;
    const char* wh = (const char*)g_wh + ((size_t)hd * FOUT + o0) * FIN * 2;

    auto stage = [&](int kc, uint32_t off) {
#pragma unroll
        for (int it = 0; it < 4; it++) {
            int idx = tid + it * 256;
            int r = idx >> 3, ch = idx & 7;
            size_t gb = ((size_t)r * FIN + kc) * 2 + ch * 16;
            uint32_t so = off + r * 128 + ((ch ^ (r & 7)) << 4);
            CPA16(sb + G_A + so, xh + gb);
            CPA16(sb + G_B + so, wh + gb);
        }
    };

    const int lt = lane >> 3;
    const int lr = lane & 7;

    stage(0, 0);
    CP_COMMIT();

    for (int ck = 0; ck < 8; ck++) {
        CP_WAIT0();
        __syncthreads();
        if (ck < 7) { stage((ck + 1) * 64, (ck & 1) ? 0u : (uint32_t)G_STAGE); CP_COMMIT(); }

        const uint32_t abase = sb + G_A + ((ck & 1) ? G_STAGE : 0);
        const uint32_t bbase = sb + G_B + ((ck & 1) ? G_STAGE : 0);

#pragma unroll
        for (int kk = 0; kk < 64; kk += 16) {
            const int kch = kk >> 3;
            uint32_t ah[2][4];
#pragma unroll
            for (int mi = 0; mi < 2; mi++) {
                int row = warp_m + mi * 16 + (lt & 1) * 8 + lr;
                LDMX4(ah[mi][0], ah[mi][1], ah[mi][2], ah[mi][3],
                      lmaddr(abase, row, kch + (lt >> 1)));
            }
#pragma unroll
            for (int pr = 0; pr < 4; pr++) {
                int row = warp_n + pr * 16 + (lt & 1) * 8 + lr;
                uint32_t bh0, bh1, bh2, bh3;
                LDMX4(bh0, bh1, bh2, bh3, lmaddr(bbase, row, kch + (lt >> 1)));
#pragma unroll
                for (int mi = 0; mi < 2; mi++) {
                    MMA16816(d[mi][2 * pr],     ah[mi][0], ah[mi][1], ah[mi][2], ah[mi][3], bh0, bh2);
                    MMA16816(d[mi][2 * pr + 1], ah[mi][0], ah[mi][1], ah[mi][2], ah[mi][3], bh1, bh3);
                }
            }
        }
    }

    const int g = lane >> 2, t = lane & 3;
    const size_t hbase = (size_t)hd * BB * NN;
#pragma unroll
    for (int mi = 0; mi < 2; mi++) {
#pragma unroll
        for (int nj = 0; nj < 8; nj++) {
            int row = m0 + warp_m + mi * 16 + g;
            int col = o0 + warp_n + nj * 8 + 2 * t;
#pragma unroll
            for (int half = 0; half < 2; half++) {
                unsigned q;
                CVT_BF2(q, d[mi][nj][half * 2 + 1], d[mi][nj][half * 2]);
                size_t off = (hbase + row + half * 8) * FOUT + col;
                *(unsigned*)(g_hh + off) = q;
            }
        }
    }
}

// ---------------------------------------------------------------------------
// Kernel 3: attn via mma.sync, triple-buffered, 2m x 8n warps, fragment-
// double-buffered inner loop (LDSM(ks+1) issues before MMA(ks) consumes).
// ---------------------------------------------------------------------------
#define AS_HB0  0
#define AS_HB1  32768
#define AS_HB2  65536
#define AS_PB0  98304
#define AS_PB1  106496
#define AS_PB2  114688
#define AS_F2   122880
#define AS_MSK  126976
#define AS_F1   135168
#define AS_RED  135424
#define AS_RED2 137472
#define AS_INV  139520
#define AS_ROWM 139776
#define AS_LSE  140032
#define AS_TOTAL 140288

__global__ __launch_bounds__(512, 1) void attn_mma(const int* __restrict__ adj,
                                                   float* __restrict__ out)
{
    extern __shared__ char sm[];
    const uint32_t sb = smem_u32(sm);
    float*    f2_s  = (float*)(sm + AS_F2);
    float*    f1_s  = (float*)(sm + AS_F1);
    unsigned* mskw  = (unsigned*)(sm + AS_MSK);
    float*    red   = (float*)(sm + AS_RED);   // [64][8]
    float*    red2  = (float*)(sm + AS_RED2);  // [64][8]
    float*    inv_s = (float*)(sm + AS_INV);
    float*    rowm  = (float*)(sm + AS_ROWM);
    float*    lse   = (float*)(sm + AS_LSE);

    const int tid  = threadIdx.x;
    const int lane = tid & 31;
    const int wid  = tid >> 5;
    const int wm   = wid & 1;
    const int wn   = wid >> 1;
    const int b    = blockIdx.y;
    const int n0   = blockIdx.x * 64;

    const int prow8 = tid >> 3;
    const int k8    = tid & 7;

    const int l7   = lane & 7;
    const int lrow = l7 + ((lane >> 3) & 1) * 8;
    const int lch  = lane >> 4;
    uint32_t arow_off[2], axoff[4], bxoff[2];
#pragma unroll
    for (int mi = 0; mi < 2; mi++)
        arow_off[mi] = (uint32_t)((wm * 32 + mi * 16 + lrow) * 128);
#pragma unroll
    for (int k = 0; k < 4; k++)
        axoff[k] = (uint32_t)((((k << 1) + lch) ^ l7) << 4);
#pragma unroll
    for (int nt = 0; nt < 2; nt++)
        bxoff[nt] = (uint32_t)(((wn * 4 + nt * 2 + lch) ^ l7) << 4);
    const uint32_t brow_off = (uint32_t)(lrow * 512);

    for (int pass = 0; pass < 128; pass++) {
        int row = pass >> 1;
        int m = ((pass & 1) << 9) + tid;
        int a = adj[((size_t)b * NN + n0 + row) * NN + m];
        unsigned w = __ballot_sync(0xffffffffu, a == 0);
        if (lane == 0) mskw[row * 32 + (m >> 5)] = w;
    }

    float tot[2][4][4];
#pragma unroll
    for (int mi = 0; mi < 2; mi++)
#pragma unroll
        for (int j = 0; j < 4; j++)
#pragma unroll
            for (int c = 0; c < 4; c++) tot[mi][j][c] = 0.f;

    const int g = lane >> 2, t4 = lane & 3;

    float psum = 0.f;

    auto cp_h = [&](const __nv_bfloat16* hsrc, int ck, int hOff) {
#pragma unroll
        for (int i = 0; i < 4; i++) {
            int idx = tid + 512 * i;
            int r = idx >> 5, cc = idx & 31;
            uint32_t dst = sb + hOff + r * 512 + ((cc ^ (r & 7)) << 4);
            CPA16(dst, (const char*)(hsrc + (size_t)(ck * 64 + r) * FOUT) + cc * 16);
        }
    };
    auto pgen = [&](int ck, int pOff, float f1v) {
        unsigned word = mskw[prow8 * 32 + (ck << 1) + (k8 >> 2)];
        unsigned byte = (word >> ((k8 & 3) << 3)) & 0xffu;
        const int kc = ck * 64;
        const float4 fa = *(const float4*)(f2_s + kc + k8 * 8);
        const float4 fb = *(const float4*)(f2_s + kc + k8 * 8 + 4);
        const float f2v[8] = {fa.x, fa.y, fa.z, fa.w, fb.x, fb.y, fb.z, fb.w};
        float pv[8];
#pragma unroll
        for (int j = 0; j < 8; j++) {
            float e = f1v + f2v[j];
            e = (e > 0.f) ? e : ALPHA * e;
            float p = ((byte >> j) & 1u) ? 0.f : __expf(e);
            pv[j] = p;
            psum += p;
        }
        uint4 q;
        CVT_BF2(q.x, pv[1], pv[0]);
        CVT_BF2(q.y, pv[3], pv[2]);
        CVT_BF2(q.z, pv[5], pv[4]);
        CVT_BF2(q.w, pv[7], pv[6]);
        *(uint4*)(sm + pOff + prow8 * 128 + ((k8 ^ (prow8 & 7)) << 4)) = q;
    };

    for (int hd = 0; hd < H; hd++) {
        const int base = (hd * BB + b) * NN;
        const __nv_bfloat16* hsrc = g_hh + (size_t)base * FOUT;

        __syncthreads();
        f2_s[tid] = g_f2[base + tid];
        f2_s[tid + 512] = g_f2[base + tid + 512];
        if (tid < 64) f1_s[tid] = g_f1[base + n0 + tid];

        int hOffA = AS_HB0, hOffB = AS_HB1, hOffC = AS_HB2;
        int pOffA = AS_PB0, pOffB = AS_PB1, pOffC = AS_PB2;

        cp_h(hsrc, 0, hOffA); CP_COMMIT();
        __syncthreads();
        psum = 0.f;
        const float f1v = f1_s[prow8];
        pgen(0, pOffA, f1v);
        cp_h(hsrc, 1, hOffB); CP_COMMIT();

        float d[2][4][4];
#pragma unroll
        for (int mi = 0; mi < 2; mi++)
#pragma unroll
            for (int j = 0; j < 4; j++)
#pragma unroll
                for (int c = 0; c < 4; c++) d[mi][j][c] = 0.f;

        // Hazard audit: mod-3 buffers, skew <= 1 iter (see R13 comment).
        for (int ck = 0; ck < 16; ck++) {
            if (ck == 15) { CP_WAIT0(); } else { CP_WAIT1(); }
            __syncthreads();
            if (ck + 2 < 16) { cp_h(hsrc, ck + 2, hOffC); CP_COMMIT(); }
            if (ck + 1 < 16) pgen(ck + 1, pOffB, f1v);

            const uint32_t pbb = sb + pOffA;
            const uint32_t hbb = sb + hOffA + brow_off;

            // fragment-double-buffered over ks: load(ks+1) before MMA(ks)
            uint32_t aF[2][2][4], bF[2][2][4];
#pragma unroll
            for (int mi = 0; mi < 2; mi++)
                LDMX4(aF[0][mi][0], aF[0][mi][1], aF[0][mi][2], aF[0][mi][3],
                      pbb + arow_off[mi] + axoff[0]);
#pragma unroll
            for (int nt = 0; nt < 2; nt++)
                LDMX4T(bF[0][nt][0], bF[0][nt][1], bF[0][nt][2], bF[0][nt][3],
                       hbb + bxoff[nt]);
#pragma unroll
            for (int i = 0; i < 4; i++) {
                const int cur = i & 1, nxt = cur ^ 1;
                if (i < 3) {
#pragma unroll
                    for (int mi = 0; mi < 2; mi++)
                        LDMX4(aF[nxt][mi][0], aF[nxt][mi][1], aF[nxt][mi][2], aF[nxt][mi][3],
                              pbb + arow_off[mi] + axoff[i + 1]);
#pragma unroll
                    for (int nt = 0; nt < 2; nt++)
                        LDMX4T(bF[nxt][nt][0], bF[nxt][nt][1], bF[nxt][nt][2], bF[nxt][nt][3],
                               hbb + (i + 1) * 16 * 512 + bxoff[nt]);
                }
#pragma unroll
                for (int nt = 0; nt < 2; nt++)
#pragma unroll
                    for (int mi = 0; mi < 2; mi++) {
                        MMA16816(d[mi][2 * nt],     aF[cur][mi][0], aF[cur][mi][1], aF[cur][mi][2], aF[cur][mi][3],
                                 bF[cur][nt][0], bF[cur][nt][1]);
                        MMA16816(d[mi][2 * nt + 1], aF[cur][mi][0], aF[cur][mi][1], aF[cur][mi][2], aF[cur][mi][3],
                                 bF[cur][nt][2], bF[cur][nt][3]);
                    }
            }
            int t = hOffA; hOffA = hOffB; hOffB = hOffC; hOffC = t;
            t = pOffA; pOffA = pOffB; pOffB = pOffC; pOffC = t;
        }

        red[prow8 * 8 + k8] = psum;
        __syncthreads();
        if (tid < 64) {
            float s = 0.f;
#pragma unroll
            for (int j = 0; j < 8; j++) s += red[tid * 8 + j];
            inv_s[tid] = 1.f / s;
        }
        __syncthreads();

#pragma unroll
        for (int mi = 0; mi < 2; mi++) {
            const int rb = wm * 32 + mi * 16 + g;
            const float i0 = inv_s[rb], i1 = inv_s[rb + 8];
#pragma unroll
            for (int j = 0; j < 4; j++) {
                float v0 = d[mi][j][0] * i0, v1 = d[mi][j][1] * i0;
                float v2 = d[mi][j][2] * i1, v3 = d[mi][j][3] * i1;
                tot[mi][j][0] += (v0 > 0.f) ? v0 : (__expf(v0) - 1.f);
                tot[mi][j][1] += (v1 > 0.f) ? v1 : (__expf(v1) - 1.f);
                tot[mi][j][2] += (v2 > 0.f) ? v2 : (__expf(v2) - 1.f);
                tot[mi][j][3] += (v3 > 0.f) ? v3 : (__expf(v3) - 1.f);
            }
        }
    }

    // ---- fused log_softmax over o (256 cols) for 64 rows ----
    __syncthreads();
#pragma unroll
    for (int mi = 0; mi < 2; mi++) {
#pragma unroll
        for (int half = 0; half < 2; half++) {
            float vm = -3.0e38f;
#pragma unroll
            for (int j = 0; j < 4; j++)
                vm = fmaxf(vm, fmaxf(tot[mi][j][half * 2], tot[mi][j][half * 2 + 1]));
            vm = fmaxf(vm, __shfl_xor_sync(0xffffffffu, vm, 1));
            vm = fmaxf(vm, __shfl_xor_sync(0xffffffffu, vm, 2));
            if (t4 == 0) red[(wm * 32 + mi * 16 + half * 8 + g) * 8 + wn] = vm;
        }
    }
    __syncthreads();
    if (tid < 64) {
        float v = red[tid * 8];
#pragma unroll
        for (int j = 1; j < 8; j++) v = fmaxf(v, red[tid * 8 + j]);
        rowm[tid] = v;
    }
    __syncthreads();
#pragma unroll
    for (int mi = 0; mi < 2; mi++) {
#pragma unroll
        for (int half = 0; half < 2; half++) {
            const float rm = rowm[wm * 32 + mi * 16 + half * 8 + g];
            float s = 0.f;
#pragma unroll
            for (int j = 0; j < 4; j++)
                s += __expf(tot[mi][j][half * 2] - rm) + __expf(tot[mi][j][half * 2 + 1] - rm);
            s += __shfl_xor_sync(0xffffffffu, s, 1);
            s += __shfl_xor_sync(0xffffffffu, s, 2);
            if (t4 == 0) red2[(wm * 32 + mi * 16 + half * 8 + g) * 8 + wn] = s;
        }
    }
    __syncthreads();
    if (tid < 64) {
        float v = 0.f;
#pragma unroll
        for (int j = 0; j < 8; j++) v += red2[tid * 8 + j];
        lse[tid] = logf(v);
    }
    __syncthreads();
#pragma unroll
    for (int mi = 0; mi < 2; mi++) {
#pragma unroll
        for (int half = 0; half < 2; half++) {
            const int row = wm * 32 + mi * 16 + half * 8 + g;
            const float c = rowm[row] + lse[row];
            float* op = out + ((size_t)b * NN + n0 + row) * FOUT;
#pragma unroll
            for (int j = 0; j < 4; j++) {
                int col = wn * 32 + j * 8 + 2 * t4;
                *(float2*)(op + col) = make_float2(tot[mi][j][half * 2] - c,
                                                   tot[mi][j][half * 2 + 1] - c);
            }
        }
    }
}

// ---------------------------------------------------------------------------
extern "C" void kernel_launch(void* const* d_in, const int* in_sizes, int n_in,
                              void* d_out, int out_size)
{
    const float* x   = (const float*)d_in[0];
    const int*   adj = (const int*)d_in[1];
    const float* W   = (const float*)d_in[2];
    const float* a1  = (const float*)d_in[3];
    const float* a2  = (const float*)d_in[4];
    float* out = (float*)d_out;

    (void)in_sizes; (void)n_in; (void)out_size;

    cudaFuncSetAttribute(prepB_kernel, cudaFuncAttributeMaxDynamicSharedMemorySize, G_TOTAL);
    cudaFuncSetAttribute(attn_mma, cudaFuncAttributeMaxDynamicSharedMemorySize, AS_TOTAL);

    prepA_kernel<<<SPLIT_BLOCKS + 8, 512>>>(x, W, a1, a2);
    prepB_kernel<<<dim3(64, 4, 8), 256, G_TOTAL>>>(x);
    attn_mma<<<dim3(16, 8), 512, AS_TOTAL>>>(adj, out);
}